// round 2
// baseline (speedup 1.0000x reference)
#include <cuda_runtime.h>
#include <cuda_bf16.h>
#include <math.h>

// ---------------------------------------------------------------------------
// Problem constants
// ---------------------------------------------------------------------------
#define BATCH   16
#define LT      512
#define LI      576
#define TEXTD   768
#define IMGD    1024
#define HID     2048
#define HEADS   8
#define HDIM    256
#define FFD     128

#define MQ (BATCH*LT)   // 8192
#define MK (BATCH*LI)   // 9216

// ---------------------------------------------------------------------------
// Device scratch (static globals: allocation-free per harness rules)
// ---------------------------------------------------------------------------
__device__ float g_Q[(size_t)MQ * HID];   // 8192 x 2048
__device__ float g_K[(size_t)MK * HID];   // 9216 x 2048
__device__ float g_V[(size_t)MK * HID];   // 9216 x 2048
__device__ float g_X[(size_t)MQ * HID];   // attn output, 8192 x 2048
__device__ float g_O[(size_t)MQ * TEXTD]; // out proj, 8192 x 768

// ---------------------------------------------------------------------------
// Generic tiled fp32 GEMM with bias: C[M,N] = A[M,K] @ B[K,N] + bias[N]
// 64x64 block tile, 16 K-slice, 256 threads, 4x4 per-thread micro-tile.
// M,N,K must be multiples of 64/64/16 (true for all call sites).
// ---------------------------------------------------------------------------
__global__ __launch_bounds__(256) void gemm_bias_kernel(
    const float* __restrict__ A, const float* __restrict__ B,
    const float* __restrict__ bias, float* __restrict__ C,
    int M, int N, int K)
{
    __shared__ float As[16][64];  // transposed A tile: As[k][m]
    __shared__ float Bs[16][64];  // Bs[k][n]

    int tid = threadIdx.x;
    int tm = tid >> 4;          // 0..15
    int tn = tid & 15;          // 0..15
    int bm = blockIdx.y * 64;
    int bn = blockIdx.x * 64;

    // load assignments
    int lam = tid >> 2;          // 0..63 : A row within tile
    int lac = (tid & 3) * 4;     // 0,4,8,12 : k offset
    int lbk = tid >> 4;          // 0..15 : B k-row
    int lbn = (tid & 15) * 4;    // 0..60 : B col offset

    const float* Ap = A + (size_t)(bm + lam) * K + lac;
    const float* Bp = B + (size_t)lbk * N + bn + lbn;

    float acc[4][4];
#pragma unroll
    for (int i = 0; i < 4; i++)
#pragma unroll
        for (int j = 0; j < 4; j++) acc[i][j] = 0.0f;

    for (int k0 = 0; k0 < K; k0 += 16) {
        float4 a4 = *(const float4*)(Ap + k0);
        float4 b4 = *(const float4*)(Bp + (size_t)k0 * N);
        As[lac + 0][lam] = a4.x;
        As[lac + 1][lam] = a4.y;
        As[lac + 2][lam] = a4.z;
        As[lac + 3][lam] = a4.w;
        *(float4*)&Bs[lbk][lbn] = b4;
        __syncthreads();

#pragma unroll
        for (int kk = 0; kk < 16; kk++) {
            float4 ra = *(const float4*)&As[kk][tm * 4];
            float4 rb = *(const float4*)&Bs[kk][tn * 4];
            float a[4] = {ra.x, ra.y, ra.z, ra.w};
            float b[4] = {rb.x, rb.y, rb.z, rb.w};
#pragma unroll
            for (int i = 0; i < 4; i++)
#pragma unroll
                for (int j = 0; j < 4; j++)
                    acc[i][j] += a[i] * b[j];
        }
        __syncthreads();
    }

#pragma unroll
    for (int i = 0; i < 4; i++) {
        size_t row = (size_t)(bm + tm * 4 + i);
#pragma unroll
        for (int j = 0; j < 4; j++) {
            int col = bn + tn * 4 + j;
            C[row * N + col] = acc[i][j] + bias[col];
        }
    }
}

// ---------------------------------------------------------------------------
// Fused attention: per block handles (batch, head, 16 q-rows).
//  - stage K (and later V) chunks of 32 keys TRANSPOSED in smem ([d][k])
//    so the inner-product reads are bank-conflict-free
//  - full softmax in-block (576 keys fit in smem scores buffer)
//  - P @ V with per-thread d ownership (float4 broadcast score reads)
// Dynamic smem: Qs 16x256 (4096f) + Kt 256x33 (8448f) + Ps 16x580 (9280f)
//   = 21824 floats = 87296 bytes
// ---------------------------------------------------------------------------
#define ATTN_SMEM_FLOATS (4096 + 256*33 + 16*580)
#define ATTN_SMEM_BYTES  (ATTN_SMEM_FLOATS * 4)

__global__ __launch_bounds__(256) void attn_kernel(
    const float* __restrict__ Qg, const float* __restrict__ Kg,
    const float* __restrict__ Vg, float* __restrict__ Xg)
{
    extern __shared__ float sm[];
    float* Qs = sm;                    // [16][256]
    float* Kt = sm + 4096;             // [256][33]  (K then V, transposed)
    float* Ps = sm + 4096 + 256 * 33;  // [16][580]

    const int tid = threadIdx.x;
    const int b = blockIdx.z, h = blockIdx.y;
    const int q0 = blockIdx.x * 16;
    const size_t hoff = (size_t)h * HDIM;

    // --- load Q tile (16 rows x 256 dims) ---
    const float* Qb = Qg + ((size_t)(b * LT + q0)) * HID + hoff;
    for (int i = tid; i < 16 * 64; i += 256) {
        int r = i >> 6, c = (i & 63) * 4;
        *(float4*)&Qs[r * 256 + c] = *(const float4*)(Qb + (size_t)r * HID + c);
    }

    const int kl = tid & 31;   // key lane 0..31
    const int qa = tid >> 5;   // q group 0..7 (handles rows qa and qa+8)

    // --- scores: 18 chunks of 32 keys ---
    for (int ch = 0; ch < 18; ch++) {
        __syncthreads();  // previous chunk consumed (and Qs ready gate below)
        const float* Kb = Kg + ((size_t)(b * LI + ch * 32)) * HID + hoff;
        for (int i = tid; i < 2048; i += 256) {
            int r = i >> 6;            // key 0..31
            int c = (i & 63) * 4;      // dim 0..252
            float4 v = *(const float4*)(Kb + (size_t)r * HID + c);
            Kt[(c + 0) * 33 + r] = v.x;
            Kt[(c + 1) * 33 + r] = v.y;
            Kt[(c + 2) * 33 + r] = v.z;
            Kt[(c + 3) * 33 + r] = v.w;
        }
        __syncthreads();

        float s0 = 0.0f, s1 = 0.0f;
        const float* qp0 = Qs + qa * 256;
        const float* qp1 = Qs + (qa + 8) * 256;
#pragma unroll 8
        for (int d4 = 0; d4 < 64; d4++) {
            float4 a0 = *(const float4*)(qp0 + d4 * 4);
            float4 a1 = *(const float4*)(qp1 + d4 * 4);
            float k0v = Kt[(d4 * 4 + 0) * 33 + kl];
            float k1v = Kt[(d4 * 4 + 1) * 33 + kl];
            float k2v = Kt[(d4 * 4 + 2) * 33 + kl];
            float k3v = Kt[(d4 * 4 + 3) * 33 + kl];
            s0 += a0.x * k0v + a0.y * k1v + a0.z * k2v + a0.w * k3v;
            s1 += a1.x * k0v + a1.y * k1v + a1.z * k2v + a1.w * k3v;
        }
        Ps[qa * 580 + ch * 32 + kl]       = s0 * 0.0625f;  // 1/sqrt(256)
        Ps[(qa + 8) * 580 + ch * 32 + kl] = s1 * 0.0625f;
    }
    __syncthreads();

    // --- softmax: warp w handles rows w and w+8 ---
    {
        const int lane = tid & 31, wid = tid >> 5;
        for (int rr = 0; rr < 2; rr++) {
            float* prow = Ps + (wid + rr * 8) * 580;
            float mx = -1e30f;
            for (int j = lane; j < LI; j += 32) mx = fmaxf(mx, prow[j]);
#pragma unroll
            for (int o = 16; o; o >>= 1) mx = fmaxf(mx, __shfl_xor_sync(0xffffffffu, mx, o));
            float sum = 0.0f;
            for (int j = lane; j < LI; j += 32) {
                float e = __expf(prow[j] - mx);
                prow[j] = e;
                sum += e;
            }
#pragma unroll
            for (int o = 16; o; o >>= 1) sum += __shfl_xor_sync(0xffffffffu, sum, o);
            float inv = 1.0f / sum;
            for (int j = lane; j < LI; j += 32) prow[j] *= inv;
        }
    }

    // --- P @ V : thread owns dim d = tid ---
    float acc[16];
#pragma unroll
    for (int q = 0; q < 16; q++) acc[q] = 0.0f;
    const int d = tid;

    for (int ch = 0; ch < 18; ch++) {
        __syncthreads();  // softmax done / previous V chunk consumed
        const float* Vb = Vg + ((size_t)(b * LI + ch * 32)) * HID + hoff;
        for (int i = tid; i < 2048; i += 256) {
            int r = i >> 6;
            int c = (i & 63) * 4;
            float4 v = *(const float4*)(Vb + (size_t)r * HID + c);
            Kt[(c + 0) * 33 + r] = v.x;
            Kt[(c + 1) * 33 + r] = v.y;
            Kt[(c + 2) * 33 + r] = v.z;
            Kt[(c + 3) * 33 + r] = v.w;
        }
        __syncthreads();

#pragma unroll 2
        for (int jg = 0; jg < 8; jg++) {
            float v0 = Kt[d * 33 + jg * 4 + 0];
            float v1 = Kt[d * 33 + jg * 4 + 1];
            float v2 = Kt[d * 33 + jg * 4 + 2];
            float v3 = Kt[d * 33 + jg * 4 + 3];
#pragma unroll
            for (int q = 0; q < 16; q++) {
                float4 p4 = *(const float4*)&Ps[q * 580 + ch * 32 + jg * 4];
                acc[q] += p4.x * v0 + p4.y * v1 + p4.z * v2 + p4.w * v3;
            }
        }
    }

    float* Xb = Xg + ((size_t)(b * LT + q0)) * HID + hoff + d;
#pragma unroll
    for (int q = 0; q < 16; q++) Xb[(size_t)q * HID] = acc[q];
}

// ---------------------------------------------------------------------------
// Fused FF + residual + LayerNorm.  4 rows per block, 256 threads.
//   h  = relu(o @ w1 + b1)          (768 -> 128)
//   y  = o + h @ w2 + b2            (128 -> 768)
//   out= LN(y) * gamma + beta
// ---------------------------------------------------------------------------
__global__ __launch_bounds__(256) void ffln_kernel(
    const float* __restrict__ O, const float* __restrict__ w1,
    const float* __restrict__ b1, const float* __restrict__ w2,
    const float* __restrict__ b2, const float* __restrict__ gamma,
    const float* __restrict__ beta, float* __restrict__ out)
{
    __shared__ float xs[4][TEXTD];
    __shared__ float hs[4][FFD];
    __shared__ float reds[4][8], redq[4][8];
    __shared__ float s_mu[4], s_rstd[4];

    const int tid = threadIdx.x;
    const size_t row0 = (size_t)blockIdx.x * 4;

    // load 4 input rows
    for (int i = tid; i < 4 * (TEXTD / 4); i += 256) {
        int r = i / (TEXTD / 4), c = (i % (TEXTD / 4)) * 4;
        *(float4*)&xs[r][c] = *(const float4*)(O + (row0 + r) * TEXTD + c);
    }
    __syncthreads();

    // hidden layer: threads 0..127 each own one hidden unit
    if (tid < FFD) {
        const int u = tid;
        float a0 = b1[u], a1 = b1[u], a2 = b1[u], a3 = b1[u];
        for (int dd = 0; dd < TEXTD; dd++) {
            float w = w1[dd * FFD + u];
            a0 += xs[0][dd] * w;
            a1 += xs[1][dd] * w;
            a2 += xs[2][dd] * w;
            a3 += xs[3][dd] * w;
        }
        hs[0][u] = fmaxf(a0, 0.0f);
        hs[1][u] = fmaxf(a1, 0.0f);
        hs[2][u] = fmaxf(a2, 0.0f);
        hs[3][u] = fmaxf(a3, 0.0f);
    }
    __syncthreads();

    // ff output + residual: thread owns cols tid, tid+256, tid+512
    float acc[4][3];
#pragma unroll
    for (int r = 0; r < 4; r++)
#pragma unroll
        for (int c = 0; c < 3; c++) acc[r][c] = 0.0f;

    for (int u = 0; u < FFD; u++) {
        float wa = w2[(size_t)u * TEXTD + tid];
        float wb = w2[(size_t)u * TEXTD + tid + 256];
        float wc = w2[(size_t)u * TEXTD + tid + 512];
#pragma unroll
        for (int r = 0; r < 4; r++) {
            float hv = hs[r][u];
            acc[r][0] += hv * wa;
            acc[r][1] += hv * wb;
            acc[r][2] += hv * wc;
        }
    }

    float yv[4][3];
#pragma unroll
    for (int r = 0; r < 4; r++) {
#pragma unroll
        for (int c = 0; c < 3; c++) {
            int n = tid + c * 256;
            yv[r][c] = xs[r][n] + acc[r][c] + b2[n];
        }
    }

    // per-row mean / var via block reduction
    const int lane = tid & 31, wid = tid >> 5;
#pragma unroll
    for (int r = 0; r < 4; r++) {
        float s = yv[r][0] + yv[r][1] + yv[r][2];
        float q = yv[r][0] * yv[r][0] + yv[r][1] * yv[r][1] + yv[r][2] * yv[r][2];
#pragma unroll
        for (int o = 16; o; o >>= 1) {
            s += __shfl_xor_sync(0xffffffffu, s, o);
            q += __shfl_xor_sync(0xffffffffu, q, o);
        }
        if (lane == 0) { reds[r][wid] = s; redq[r][wid] = q; }
    }
    __syncthreads();
    if (tid < 4) {
        float s = 0.0f, q = 0.0f;
#pragma unroll
        for (int w = 0; w < 8; w++) { s += reds[tid][w]; q += redq[tid][w]; }
        float m = s * (1.0f / TEXTD);
        float v = q * (1.0f / TEXTD) - m * m;
        s_mu[tid] = m;
        s_rstd[tid] = rsqrtf(v + 1e-5f);
    }
    __syncthreads();

#pragma unroll
    for (int r = 0; r < 4; r++) {
        float m = s_mu[r], rs = s_rstd[r];
#pragma unroll
        for (int c = 0; c < 3; c++) {
            int n = tid + c * 256;
            out[(row0 + r) * TEXTD + n] = (yv[r][c] - m) * rs * gamma[n] + beta[n];
        }
    }
}

// ---------------------------------------------------------------------------
// Launcher
// ---------------------------------------------------------------------------
extern "C" void kernel_launch(void* const* d_in, const int* in_sizes, int n_in,
                              void* d_out, int out_size)
{
    const float* text  = (const float*)d_in[0];
    const float* image = (const float*)d_in[1];
    const float* wq = (const float*)d_in[2];
    const float* bq = (const float*)d_in[3];
    const float* wk = (const float*)d_in[4];
    const float* bk = (const float*)d_in[5];
    const float* wv = (const float*)d_in[6];
    const float* bv = (const float*)d_in[7];
    const float* wr = (const float*)d_in[8];
    const float* br = (const float*)d_in[9];
    const float* w1 = (const float*)d_in[10];
    const float* b1 = (const float*)d_in[11];
    const float* w2 = (const float*)d_in[12];
    const float* b2 = (const float*)d_in[13];
    const float* gamma = (const float*)d_in[14];
    const float* beta  = (const float*)d_in[15];
    float* out = (float*)d_out;

    float *Qp, *Kp, *Vp, *Xp, *Op;
    cudaGetSymbolAddress((void**)&Qp, g_Q);
    cudaGetSymbolAddress((void**)&Kp, g_K);
    cudaGetSymbolAddress((void**)&Vp, g_V);
    cudaGetSymbolAddress((void**)&Xp, g_X);
    cudaGetSymbolAddress((void**)&Op, g_O);

    cudaFuncSetAttribute(attn_kernel, cudaFuncAttributeMaxDynamicSharedMemorySize,
                         ATTN_SMEM_BYTES);

    // Q = text @ wq + bq            [8192 x 2048]
    gemm_bias_kernel<<<dim3(HID / 64, MQ / 64), 256>>>(text, wq, bq, Qp, MQ, HID, TEXTD);
    // K = image @ wk + bk           [9216 x 2048]
    gemm_bias_kernel<<<dim3(HID / 64, MK / 64), 256>>>(image, wk, bk, Kp, MK, HID, IMGD);
    // V = image @ wv + bv           [9216 x 2048]
    gemm_bias_kernel<<<dim3(HID / 64, MK / 64), 256>>>(image, wv, bv, Vp, MK, HID, IMGD);
    // attention                      [8192 x 2048]
    attn_kernel<<<dim3(LT / 16, HEADS, BATCH), 256, ATTN_SMEM_BYTES>>>(Qp, Kp, Vp, Xp);
    // out = X @ wr + br             [8192 x 768]
    gemm_bias_kernel<<<dim3(TEXTD / 64, MQ / 64), 256>>>(Xp, wr, br, Op, MQ, TEXTD, HID);
    // FF + residual + LayerNorm -> d_out
    ffln_kernel<<<MQ / 4, 256>>>(Op, w1, b1, w2, b2, gamma, beta, out);
}

// round 5
// speedup vs baseline: 1.6235x; 1.6235x over previous
#include <cuda_runtime.h>
#include <cuda_bf16.h>
#include <math.h>
#include <stdint.h>

// ---------------------------------------------------------------------------
// Problem constants
// ---------------------------------------------------------------------------
#define BATCH   16
#define LT      512
#define LI      576
#define TEXTD   768
#define IMGD    1024
#define HID     2048
#define HEADS   8
#define HDIM    256
#define FFD     128

#define MQ (BATCH*LT)   // 8192
#define MK (BATCH*LI)   // 9216

// ---------------------------------------------------------------------------
// Device scratch
// ---------------------------------------------------------------------------
__device__ float g_Q[(size_t)MQ * HID];
__device__ float g_K[(size_t)MK * HID];
__device__ float g_V[(size_t)MK * HID];
__device__ float g_X[(size_t)MQ * HID];
__device__ float g_O[(size_t)MQ * TEXTD];

// split bf16 activations (hi/lo)
__device__ __nv_bfloat16 g_th[(size_t)MQ * TEXTD], g_tl[(size_t)MQ * TEXTD];
__device__ __nv_bfloat16 g_ih[(size_t)MK * IMGD],  g_il[(size_t)MK * IMGD];
__device__ __nv_bfloat16 g_xh[(size_t)MQ * HID],   g_xl[(size_t)MQ * HID];
// split bf16 transposed weights [N,K]
__device__ __nv_bfloat16 g_wqh[(size_t)HID * TEXTD], g_wql[(size_t)HID * TEXTD];
__device__ __nv_bfloat16 g_wkh[(size_t)HID * IMGD],  g_wkl[(size_t)HID * IMGD];
__device__ __nv_bfloat16 g_wvh[(size_t)HID * IMGD],  g_wvl[(size_t)HID * IMGD];
__device__ __nv_bfloat16 g_wrh[(size_t)TEXTD * HID], g_wrl[(size_t)TEXTD * HID];

// ---------------------------------------------------------------------------
// PTX helpers (arch-neutral: ldmatrix / mma.sync / cp.async)
// ---------------------------------------------------------------------------
__device__ __forceinline__ uint32_t smem_u32(const void* p) {
    uint32_t a;
    asm("{ .reg .u64 t; cvta.to.shared.u64 t, %1; cvt.u32.u64 %0, t; }"
        : "=r"(a) : "l"(p));
    return a;
}

__device__ __forceinline__ void ldm_x4(uint32_t* r, uint32_t addr) {
    asm volatile("ldmatrix.sync.aligned.m8n8.x4.shared.b16 {%0,%1,%2,%3}, [%4];"
                 : "=r"(r[0]), "=r"(r[1]), "=r"(r[2]), "=r"(r[3]) : "r"(addr));
}

__device__ __forceinline__ void mma16816(float* d, const uint32_t* a,
                                         const uint32_t* b) {
    asm volatile(
        "mma.sync.aligned.m16n8k16.row.col.f32.bf16.bf16.f32 "
        "{%0,%1,%2,%3}, {%4,%5,%6,%7}, {%8,%9}, {%0,%1,%2,%3};"
        : "+f"(d[0]), "+f"(d[1]), "+f"(d[2]), "+f"(d[3])
        : "r"(a[0]), "r"(a[1]), "r"(a[2]), "r"(a[3]), "r"(b[0]), "r"(b[1]));
}

#define CP_ASYNC16(smem, gptr) \
    asm volatile("cp.async.cg.shared.global [%0], [%1], 16;" \
        :: "r"(smem), "l"(gptr) : "memory")
#define CP_COMMIT() asm volatile("cp.async.commit_group;" ::: "memory")
#define CP_WAIT(n)  asm volatile("cp.async.wait_group %0;" :: "n"(n) : "memory")

// ---------------------------------------------------------------------------
// Split fp32 -> bf16 hi + bf16 lo (elementwise, vectorized by 4)
// ---------------------------------------------------------------------------
__global__ __launch_bounds__(256) void cvt_split(
    const float4* __restrict__ x, __nv_bfloat162* __restrict__ h,
    __nv_bfloat162* __restrict__ l, int n4)
{
    int i = blockIdx.x * 256 + threadIdx.x;
    if (i >= n4) return;
    float4 v = x[i];
    __nv_bfloat16 h0 = __float2bfloat16(v.x), h1 = __float2bfloat16(v.y);
    __nv_bfloat16 h2 = __float2bfloat16(v.z), h3 = __float2bfloat16(v.w);
    __nv_bfloat16 l0 = __float2bfloat16(v.x - __bfloat162float(h0));
    __nv_bfloat16 l1 = __float2bfloat16(v.y - __bfloat162float(h1));
    __nv_bfloat16 l2 = __float2bfloat16(v.z - __bfloat162float(h2));
    __nv_bfloat16 l3 = __float2bfloat16(v.w - __bfloat162float(h3));
    h[2 * i]     = __halves2bfloat162(h0, h1);
    h[2 * i + 1] = __halves2bfloat162(h2, h3);
    l[2 * i]     = __halves2bfloat162(l0, l1);
    l[2 * i + 1] = __halves2bfloat162(l2, l3);
}

// ---------------------------------------------------------------------------
// Transpose + split: w[K,N] fp32 -> hT[N,K], lT[N,K] bf16
// ---------------------------------------------------------------------------
__global__ void cvt_trans(const float* __restrict__ w,
                          __nv_bfloat16* __restrict__ h,
                          __nv_bfloat16* __restrict__ l, int K, int N)
{
    __shared__ float t[32][33];
    int n0 = blockIdx.x * 32, k0 = blockIdx.y * 32;
    int tx = threadIdx.x, ty = threadIdx.y;
#pragma unroll
    for (int i = 0; i < 4; i++)
        t[ty + 8 * i][tx] = w[(size_t)(k0 + ty + 8 * i) * N + n0 + tx];
    __syncthreads();
#pragma unroll
    for (int i = 0; i < 4; i++) {
        float v = t[tx][ty + 8 * i];
        __nv_bfloat16 hb = __float2bfloat16(v);
        __nv_bfloat16 lb = __float2bfloat16(v - __bfloat162float(hb));
        size_t o = (size_t)(n0 + ty + 8 * i) * K + k0 + tx;
        h[o] = hb;
        l[o] = lb;
    }
}

// ---------------------------------------------------------------------------
// bf16x3 HMMA GEMM:  C[M,N] = (Ah+Al)[M,K] @ (Bh+Bl)[N,K]^T + bias[N]
// CTA 128x128, 8 warps (2M x 4N), warp tile 64x32, KC=64, cp.async x2 buffer.
// smem row stride 144B -> conflict-free ldmatrix.
// ---------------------------------------------------------------------------
#define KC       64
#define RSTRIDE  144                 // bytes per smem row (64 bf16 + pad)
#define ARRB     (128 * RSTRIDE)     // 18432 bytes per array
#define STAGEB   (4 * ARRB)          // Ah,Al,Bh,Bl : 73728 bytes
#define GSMEM    (2 * STAGEB)        // 147456

__device__ __forceinline__ void g_load_stage(
    uint32_t sb, int st, const __nv_bfloat16* Ah, const __nv_bfloat16* Al,
    const __nv_bfloat16* Bh, const __nv_bfloat16* Bl,
    int m0, int n0, int k0, int K, int tid)
{
    uint32_t base = sb + (uint32_t)st * STAGEB;
#pragma unroll 4
    for (int i = tid; i < 4096; i += 256) {
        int arr = i >> 10;          // 0..3
        int idx = i & 1023;
        int row = idx >> 3;
        int c   = idx & 7;          // 16B chunk within row
        const __nv_bfloat16* g;
        if (arr == 0)      g = Ah + (size_t)(m0 + row) * K;
        else if (arr == 1) g = Al + (size_t)(m0 + row) * K;
        else if (arr == 2) g = Bh + (size_t)(n0 + row) * K;
        else               g = Bl + (size_t)(n0 + row) * K;
        const __nv_bfloat16* gp = g + k0 + c * 8;
        uint32_t sm = base + (uint32_t)arr * ARRB + (uint32_t)row * RSTRIDE + c * 16;
        CP_ASYNC16(sm, gp);
    }
}

__global__ __launch_bounds__(256, 1)
void gemm_bf16x3(const __nv_bfloat16* __restrict__ Ah,
                 const __nv_bfloat16* __restrict__ Al,
                 const __nv_bfloat16* __restrict__ Bh,
                 const __nv_bfloat16* __restrict__ Bl,
                 const float* __restrict__ bias, float* __restrict__ C,
                 int M, int N, int K)
{
    extern __shared__ char smem[];
    uint32_t sb = smem_u32(smem);
    const int tid = threadIdx.x;
    const int wid = tid >> 5;
    const int lane = tid & 31;
    const int wm = wid & 1;          // 0..1 -> 64-row half
    const int wn = wid >> 1;         // 0..3 -> 32-col quarter
    const int m0 = blockIdx.y * 128;
    const int n0 = blockIdx.x * 128;

    float acc[4][4][4];
#pragma unroll
    for (int mi = 0; mi < 4; mi++)
#pragma unroll
        for (int ni = 0; ni < 4; ni++)
#pragma unroll
            for (int j = 0; j < 4; j++) acc[mi][ni][j] = 0.0f;

    const int S = K / KC;

    g_load_stage(sb, 0, Ah, Al, Bh, Bl, m0, n0, 0, K, tid);
    CP_COMMIT();

    // per-lane ldmatrix address offsets
    const int g8 = lane >> 3, r8 = lane & 7;
    // A: g0 rows m..m+7 @k, g1 rows m+8..15 @k, g2 rows m..+7 @k+8, g3 +8 @k+8
    const uint32_t aoff = (uint32_t)((wm * 64 + (g8 & 1) * 8 + r8) * RSTRIDE
                                     + (g8 >> 1) * 16);
    // B: g0 rows n..n+7 @k, g1 same rows @k+8, g2 rows n+8..15 @k, g3 @k+8
    const uint32_t boff = (uint32_t)((wn * 32 + (g8 >> 1) * 8 + r8) * RSTRIDE
                                     + (g8 & 1) * 16);

    for (int s = 0; s < S; s++) {
        if (s + 1 < S) {
            g_load_stage(sb, (s + 1) & 1, Ah, Al, Bh, Bl, m0, n0,
                         (s + 1) * KC, K, tid);
            CP_COMMIT();
            CP_WAIT(1);
        } else {
            CP_WAIT(0);
        }
        __syncthreads();

        uint32_t sA  = sb + (uint32_t)(s & 1) * STAGEB;
        uint32_t sAl = sA + ARRB;
        uint32_t sB  = sA + 2 * ARRB;
        uint32_t sBl = sA + 3 * ARRB;

#pragma unroll
        for (int ks = 0; ks < 4; ks++) {
            const uint32_t kb = ks * 32;   // 16 elements * 2B
            uint32_t ah[4][4], al[4][4];
#pragma unroll
            for (int mi = 0; mi < 4; mi++) {
                uint32_t o = aoff + (uint32_t)(mi * 16 * RSTRIDE) + kb;
                ldm_x4(ah[mi], sA + o);
                ldm_x4(al[mi], sAl + o);
            }
            uint32_t bh[2][4], bl[2][4];
#pragma unroll
            for (int nb = 0; nb < 2; nb++) {
                uint32_t o = boff + (uint32_t)(nb * 16 * RSTRIDE) + kb;
                ldm_x4(bh[nb], sB + o);
                ldm_x4(bl[nb], sBl + o);
            }
#pragma unroll
            for (int mi = 0; mi < 4; mi++) {
#pragma unroll
                for (int ni = 0; ni < 4; ni++) {
                    float* d = acc[mi][ni];
                    const uint32_t* Bh2 = &bh[ni >> 1][(ni & 1) * 2];
                    const uint32_t* Bl2 = &bl[ni >> 1][(ni & 1) * 2];
                    mma16816(d, ah[mi], Bh2);
                    mma16816(d, ah[mi], Bl2);
                    mma16816(d, al[mi], Bh2);
                }
            }
        }
        __syncthreads();
    }

    // epilogue: d regs -> C with bias
    const int er = lane >> 2;       // 0..7
    const int ec = (lane & 3) * 2;  // 0,2,4,6
#pragma unroll
    for (int mi = 0; mi < 4; mi++) {
        int row = m0 + wm * 64 + mi * 16 + er;
#pragma unroll
        for (int ni = 0; ni < 4; ni++) {
            int col = n0 + wn * 32 + ni * 8 + ec;
            float bx = bias[col], by = bias[col + 1];
            float2 v0 = make_float2(acc[mi][ni][0] + bx, acc[mi][ni][1] + by);
            float2 v1 = make_float2(acc[mi][ni][2] + bx, acc[mi][ni][3] + by);
            *(float2*)(C + (size_t)row * N + col)       = v0;
            *(float2*)(C + (size_t)(row + 8) * N + col) = v1;
        }
    }
}

// ---------------------------------------------------------------------------
// Fused attention (fp32 SIMT): block = (batch, head, 16 q-rows)
// ---------------------------------------------------------------------------
#define ATTN_SMEM_FLOATS (4096 + 256*33 + 16*580)
#define ATTN_SMEM_BYTES  (ATTN_SMEM_FLOATS * 4)

__global__ __launch_bounds__(256) void attn_kernel(
    const float* __restrict__ Qg, const float* __restrict__ Kg,
    const float* __restrict__ Vg, float* __restrict__ Xg)
{
    extern __shared__ float sm[];
    float* Qs = sm;
    float* Kt = sm + 4096;
    float* Ps = sm + 4096 + 256 * 33;

    const int tid = threadIdx.x;
    const int b = blockIdx.z, h = blockIdx.y;
    const int q0 = blockIdx.x * 16;
    const size_t hoff = (size_t)h * HDIM;

    const float* Qb = Qg + ((size_t)(b * LT + q0)) * HID + hoff;
    for (int i = tid; i < 16 * 64; i += 256) {
        int r = i >> 6, c = (i & 63) * 4;
        *(float4*)&Qs[r * 256 + c] = *(const float4*)(Qb + (size_t)r * HID + c);
    }

    const int kl = tid & 31;
    const int qa = tid >> 5;

    for (int ch = 0; ch < 18; ch++) {
        __syncthreads();
        const float* Kb = Kg + ((size_t)(b * LI + ch * 32)) * HID + hoff;
        for (int i = tid; i < 2048; i += 256) {
            int r = i >> 6;
            int c = (i & 63) * 4;
            float4 v = *(const float4*)(Kb + (size_t)r * HID + c);
            Kt[(c + 0) * 33 + r] = v.x;
            Kt[(c + 1) * 33 + r] = v.y;
            Kt[(c + 2) * 33 + r] = v.z;
            Kt[(c + 3) * 33 + r] = v.w;
        }
        __syncthreads();

        float s0 = 0.0f, s1 = 0.0f;
        const float* qp0 = Qs + qa * 256;
        const float* qp1 = Qs + (qa + 8) * 256;
#pragma unroll 8
        for (int d4 = 0; d4 < 64; d4++) {
            float4 a0 = *(const float4*)(qp0 + d4 * 4);
            float4 a1 = *(const float4*)(qp1 + d4 * 4);
            float k0v = Kt[(d4 * 4 + 0) * 33 + kl];
            float k1v = Kt[(d4 * 4 + 1) * 33 + kl];
            float k2v = Kt[(d4 * 4 + 2) * 33 + kl];
            float k3v = Kt[(d4 * 4 + 3) * 33 + kl];
            s0 += a0.x * k0v + a0.y * k1v + a0.z * k2v + a0.w * k3v;
            s1 += a1.x * k0v + a1.y * k1v + a1.z * k2v + a1.w * k3v;
        }
        Ps[qa * 580 + ch * 32 + kl]       = s0 * 0.0625f;
        Ps[(qa + 8) * 580 + ch * 32 + kl] = s1 * 0.0625f;
    }
    __syncthreads();

    {
        const int lane = tid & 31, wd = tid >> 5;
        for (int rr = 0; rr < 2; rr++) {
            float* prow = Ps + (wd + rr * 8) * 580;
            float mx = -1e30f;
            for (int j = lane; j < LI; j += 32) mx = fmaxf(mx, prow[j]);
#pragma unroll
            for (int o = 16; o; o >>= 1) mx = fmaxf(mx, __shfl_xor_sync(0xffffffffu, mx, o));
            float sum = 0.0f;
            for (int j = lane; j < LI; j += 32) {
                float e = __expf(prow[j] - mx);
                prow[j] = e;
                sum += e;
            }
#pragma unroll
            for (int o = 16; o; o >>= 1) sum += __shfl_xor_sync(0xffffffffu, sum, o);
            float inv = 1.0f / sum;
            for (int j = lane; j < LI; j += 32) prow[j] *= inv;
        }
    }

    float acc[16];
#pragma unroll
    for (int q = 0; q < 16; q++) acc[q] = 0.0f;
    const int d = tid;

    for (int ch = 0; ch < 18; ch++) {
        __syncthreads();
        const float* Vb = Vg + ((size_t)(b * LI + ch * 32)) * HID + hoff;
        for (int i = tid; i < 2048; i += 256) {
            int r = i >> 6;
            int c = (i & 63) * 4;
            float4 v = *(const float4*)(Vb + (size_t)r * HID + c);
            Kt[(c + 0) * 33 + r] = v.x;
            Kt[(c + 1) * 33 + r] = v.y;
            Kt[(c + 2) * 33 + r] = v.z;
            Kt[(c + 3) * 33 + r] = v.w;
        }
        __syncthreads();

#pragma unroll 2
        for (int jg = 0; jg < 8; jg++) {
            float v0 = Kt[d * 33 + jg * 4 + 0];
            float v1 = Kt[d * 33 + jg * 4 + 1];
            float v2 = Kt[d * 33 + jg * 4 + 2];
            float v3 = Kt[d * 33 + jg * 4 + 3];
#pragma unroll
            for (int q = 0; q < 16; q++) {
                float4 p4 = *(const float4*)&Ps[q * 580 + ch * 32 + jg * 4];
                acc[q] += p4.x * v0 + p4.y * v1 + p4.z * v2 + p4.w * v3;
            }
        }
    }

    float* Xb = Xg + ((size_t)(b * LT + q0)) * HID + hoff + d;
#pragma unroll
    for (int q = 0; q < 16; q++) Xb[(size_t)q * HID] = acc[q];
}

// ---------------------------------------------------------------------------
// Fused FF + residual + LayerNorm
// ---------------------------------------------------------------------------
__global__ __launch_bounds__(256) void ffln_kernel(
    const float* __restrict__ O, const float* __restrict__ w1,
    const float* __restrict__ b1, const float* __restrict__ w2,
    const float* __restrict__ b2, const float* __restrict__ gamma,
    const float* __restrict__ beta, float* __restrict__ out)
{
    __shared__ float xs[4][TEXTD];
    __shared__ float hs[4][FFD];
    __shared__ float reds[4][8], redq[4][8];
    __shared__ float s_mu[4], s_rstd[4];

    const int tid = threadIdx.x;
    const size_t row0 = (size_t)blockIdx.x * 4;

    for (int i = tid; i < 4 * (TEXTD / 4); i += 256) {
        int r = i / (TEXTD / 4), c = (i % (TEXTD / 4)) * 4;
        *(float4*)&xs[r][c] = *(const float4*)(O + (row0 + r) * TEXTD + c);
    }
    __syncthreads();

    if (tid < FFD) {
        const int u = tid;
        float a0 = b1[u], a1 = b1[u], a2 = b1[u], a3 = b1[u];
        for (int dd = 0; dd < TEXTD; dd++) {
            float w = w1[dd * FFD + u];
            a0 += xs[0][dd] * w;
            a1 += xs[1][dd] * w;
            a2 += xs[2][dd] * w;
            a3 += xs[3][dd] * w;
        }
        hs[0][u] = fmaxf(a0, 0.0f);
        hs[1][u] = fmaxf(a1, 0.0f);
        hs[2][u] = fmaxf(a2, 0.0f);
        hs[3][u] = fmaxf(a3, 0.0f);
    }
    __syncthreads();

    float acc[4][3];
#pragma unroll
    for (int r = 0; r < 4; r++)
#pragma unroll
        for (int c = 0; c < 3; c++) acc[r][c] = 0.0f;

    for (int u = 0; u < FFD; u++) {
        float wa = w2[(size_t)u * TEXTD + tid];
        float wb = w2[(size_t)u * TEXTD + tid + 256];
        float wc = w2[(size_t)u * TEXTD + tid + 512];
#pragma unroll
        for (int r = 0; r < 4; r++) {
            float hv = hs[r][u];
            acc[r][0] += hv * wa;
            acc[r][1] += hv * wb;
            acc[r][2] += hv * wc;
        }
    }

    float yv[4][3];
#pragma unroll
    for (int r = 0; r < 4; r++) {
#pragma unroll
        for (int c = 0; c < 3; c++) {
            int n = tid + c * 256;
            yv[r][c] = xs[r][n] + acc[r][c] + b2[n];
        }
    }

    const int lane = tid & 31, wd = tid >> 5;
#pragma unroll
    for (int r = 0; r < 4; r++) {
        float s = yv[r][0] + yv[r][1] + yv[r][2];
        float q = yv[r][0] * yv[r][0] + yv[r][1] * yv[r][1] + yv[r][2] * yv[r][2];
#pragma unroll
        for (int o = 16; o; o >>= 1) {
            s += __shfl_xor_sync(0xffffffffu, s, o);
            q += __shfl_xor_sync(0xffffffffu, q, o);
        }
        if (lane == 0) { reds[r][wd] = s; redq[r][wd] = q; }
    }
    __syncthreads();
    if (tid < 4) {
        float s = 0.0f, q = 0.0f;
#pragma unroll
        for (int w = 0; w < 8; w++) { s += reds[tid][w]; q += redq[tid][w]; }
        float m = s * (1.0f / TEXTD);
        float v = q * (1.0f / TEXTD) - m * m;
        s_mu[tid] = m;
        s_rstd[tid] = rsqrtf(v + 1e-5f);
    }
    __syncthreads();

#pragma unroll
    for (int r = 0; r < 4; r++) {
        float m = s_mu[r], rs = s_rstd[r];
#pragma unroll
        for (int c = 0; c < 3; c++) {
            int n = tid + c * 256;
            out[(row0 + r) * TEXTD + n] = (yv[r][c] - m) * rs * gamma[n] + beta[n];
        }
    }
}

// ---------------------------------------------------------------------------
// Launcher
// ---------------------------------------------------------------------------
extern "C" void kernel_launch(void* const* d_in, const int* in_sizes, int n_in,
                              void* d_out, int out_size)
{
    const float* text  = (const float*)d_in[0];
    const float* image = (const float*)d_in[1];
    const float* wq = (const float*)d_in[2];
    const float* bq = (const float*)d_in[3];
    const float* wk = (const float*)d_in[4];
    const float* bk = (const float*)d_in[5];
    const float* wv = (const float*)d_in[6];
    const float* bv = (const float*)d_in[7];
    const float* wr = (const float*)d_in[8];
    const float* br = (const float*)d_in[9];
    const float* w1 = (const float*)d_in[10];
    const float* b1 = (const float*)d_in[11];
    const float* w2 = (const float*)d_in[12];
    const float* b2 = (const float*)d_in[13];
    const float* gamma = (const float*)d_in[14];
    const float* beta  = (const float*)d_in[15];
    float* out = (float*)d_out;

    float *Qp, *Kp, *Vp, *Xp, *Op;
    cudaGetSymbolAddress((void**)&Qp, g_Q);
    cudaGetSymbolAddress((void**)&Kp, g_K);
    cudaGetSymbolAddress((void**)&Vp, g_V);
    cudaGetSymbolAddress((void**)&Xp, g_X);
    cudaGetSymbolAddress((void**)&Op, g_O);

    __nv_bfloat16 *th, *tl, *ih, *il, *xh, *xl;
    __nv_bfloat16 *wqh, *wql, *wkh, *wkl, *wvh, *wvl, *wrh, *wrl;
    cudaGetSymbolAddress((void**)&th, g_th);
    cudaGetSymbolAddress((void**)&tl, g_tl);
    cudaGetSymbolAddress((void**)&ih, g_ih);
    cudaGetSymbolAddress((void**)&il, g_il);
    cudaGetSymbolAddress((void**)&xh, g_xh);
    cudaGetSymbolAddress((void**)&xl, g_xl);
    cudaGetSymbolAddress((void**)&wqh, g_wqh);
    cudaGetSymbolAddress((void**)&wql, g_wql);
    cudaGetSymbolAddress((void**)&wkh, g_wkh);
    cudaGetSymbolAddress((void**)&wkl, g_wkl);
    cudaGetSymbolAddress((void**)&wvh, g_wvh);
    cudaGetSymbolAddress((void**)&wvl, g_wvl);
    cudaGetSymbolAddress((void**)&wrh, g_wrh);
    cudaGetSymbolAddress((void**)&wrl, g_wrl);

    cudaFuncSetAttribute(attn_kernel, cudaFuncAttributeMaxDynamicSharedMemorySize,
                         ATTN_SMEM_BYTES);
    cudaFuncSetAttribute(gemm_bf16x3, cudaFuncAttributeMaxDynamicSharedMemorySize,
                         GSMEM);

    // --- conversions ---
    {
        int n4 = MQ * TEXTD / 4;
        cvt_split<<<(n4 + 255) / 256, 256>>>((const float4*)text,
            (__nv_bfloat162*)th, (__nv_bfloat162*)tl, n4);
    }
    {
        int n4 = MK * IMGD / 4;
        cvt_split<<<(n4 + 255) / 256, 256>>>((const float4*)image,
            (__nv_bfloat162*)ih, (__nv_bfloat162*)il, n4);
    }
    cvt_trans<<<dim3(HID / 32, TEXTD / 32), dim3(32, 8)>>>(wq, wqh, wql, TEXTD, HID);
    cvt_trans<<<dim3(HID / 32, IMGD / 32),  dim3(32, 8)>>>(wk, wkh, wkl, IMGD, HID);
    cvt_trans<<<dim3(HID / 32, IMGD / 32),  dim3(32, 8)>>>(wv, wvh, wvl, IMGD, HID);
    cvt_trans<<<dim3(TEXTD / 32, HID / 32), dim3(32, 8)>>>(wr, wrh, wrl, HID, TEXTD);

    // --- projection GEMMs (HMMA bf16x3) ---
    gemm_bf16x3<<<dim3(HID / 128, MQ / 128), 256, GSMEM>>>(
        th, tl, wqh, wql, bq, Qp, MQ, HID, TEXTD);
    gemm_bf16x3<<<dim3(HID / 128, MK / 128), 256, GSMEM>>>(
        ih, il, wkh, wkl, bk, Kp, MK, HID, IMGD);
    gemm_bf16x3<<<dim3(HID / 128, MK / 128), 256, GSMEM>>>(
        ih, il, wvh, wvl, bv, Vp, MK, HID, IMGD);

    // --- attention ---
    attn_kernel<<<dim3(LT / 16, HEADS, BATCH), 256, ATTN_SMEM_BYTES>>>(Qp, Kp, Vp, Xp);

    // --- out projection ---
    {
        int n4 = MQ * HID / 4;
        cvt_split<<<(n4 + 255) / 256, 256>>>((const float4*)Xp,
            (__nv_bfloat162*)xh, (__nv_bfloat162*)xl, n4);
    }
    gemm_bf16x3<<<dim3(TEXTD / 128, MQ / 128), 256, GSMEM>>>(
        xh, xl, wrh, wrl, br, Op, MQ, TEXTD, HID);

    // --- FF + residual + LayerNorm ---
    ffln_kernel<<<MQ / 4, 256>>>(Op, w1, b1, w2, b2, gamma, beta, out);
}

// round 6
// speedup vs baseline: 3.3438x; 2.0596x over previous
#include <cuda_runtime.h>
#include <cuda_bf16.h>
#include <math.h>
#include <stdint.h>

// ---------------------------------------------------------------------------
// Problem constants
// ---------------------------------------------------------------------------
#define BATCH   16
#define LT      512
#define LI      576
#define TEXTD   768
#define IMGD    1024
#define HID     2048
#define HEADS   8
#define HDIM    256
#define FFD     128

#define MQ (BATCH*LT)   // 8192
#define MK (BATCH*LI)   // 9216

// ---------------------------------------------------------------------------
// Device scratch
// ---------------------------------------------------------------------------
__device__ float g_O[(size_t)MQ * TEXTD];

// split bf16 activations (hi/lo)
__device__ __nv_bfloat16 g_th[(size_t)MQ * TEXTD], g_tl[(size_t)MQ * TEXTD];
__device__ __nv_bfloat16 g_ih[(size_t)MK * IMGD],  g_il[(size_t)MK * IMGD];
__device__ __nv_bfloat16 g_qh[(size_t)MQ * HID],   g_ql[(size_t)MQ * HID];
__device__ __nv_bfloat16 g_kh[(size_t)MK * HID],   g_kl[(size_t)MK * HID];
__device__ __nv_bfloat16 g_vh[(size_t)MK * HID],   g_vl[(size_t)MK * HID];
__device__ __nv_bfloat16 g_xh[(size_t)MQ * HID],   g_xl[(size_t)MQ * HID];
// split bf16 transposed weights [N,K]
__device__ __nv_bfloat16 g_wqh[(size_t)HID * TEXTD], g_wql[(size_t)HID * TEXTD];
__device__ __nv_bfloat16 g_wkh[(size_t)HID * IMGD],  g_wkl[(size_t)HID * IMGD];
__device__ __nv_bfloat16 g_wvh[(size_t)HID * IMGD],  g_wvl[(size_t)HID * IMGD];
__device__ __nv_bfloat16 g_wrh[(size_t)TEXTD * HID], g_wrl[(size_t)TEXTD * HID];

// ---------------------------------------------------------------------------
// PTX helpers (arch-neutral: ldmatrix / mma.sync / cp.async)
// ---------------------------------------------------------------------------
__device__ __forceinline__ uint32_t smem_u32(const void* p) {
    uint32_t a;
    asm("{ .reg .u64 t; cvta.to.shared.u64 t, %1; cvt.u32.u64 %0, t; }"
        : "=r"(a) : "l"(p));
    return a;
}

__device__ __forceinline__ void ldm_x4(uint32_t* r, uint32_t addr) {
    asm volatile("ldmatrix.sync.aligned.m8n8.x4.shared.b16 {%0,%1,%2,%3}, [%4];"
                 : "=r"(r[0]), "=r"(r[1]), "=r"(r[2]), "=r"(r[3]) : "r"(addr));
}

__device__ __forceinline__ void ldm_x4t(uint32_t* r, uint32_t addr) {
    asm volatile("ldmatrix.sync.aligned.m8n8.x4.trans.shared.b16 {%0,%1,%2,%3}, [%4];"
                 : "=r"(r[0]), "=r"(r[1]), "=r"(r[2]), "=r"(r[3]) : "r"(addr));
}

__device__ __forceinline__ void mma16816(float* d, const uint32_t* a,
                                         const uint32_t* b) {
    asm volatile(
        "mma.sync.aligned.m16n8k16.row.col.f32.bf16.bf16.f32 "
        "{%0,%1,%2,%3}, {%4,%5,%6,%7}, {%8,%9}, {%0,%1,%2,%3};"
        : "+f"(d[0]), "+f"(d[1]), "+f"(d[2]), "+f"(d[3])
        : "r"(a[0]), "r"(a[1]), "r"(a[2]), "r"(a[3]), "r"(b[0]), "r"(b[1]));
}

#define CP_ASYNC16(smem, gptr) \
    asm volatile("cp.async.cg.shared.global [%0], [%1], 16;" \
        :: "r"(smem), "l"(gptr) : "memory")
#define CP_COMMIT() asm volatile("cp.async.commit_group;" ::: "memory")
#define CP_WAIT(n)  asm volatile("cp.async.wait_group %0;" :: "n"(n) : "memory")

__device__ __forceinline__ uint32_t pack_bf2(float a, float b) {
    __nv_bfloat162 v = __halves2bfloat162(__float2bfloat16(a), __float2bfloat16(b));
    return *(uint32_t*)&v;
}

// ---------------------------------------------------------------------------
// Split fp32 -> bf16 hi + bf16 lo (elementwise, vectorized by 4)
// ---------------------------------------------------------------------------
__global__ __launch_bounds__(256) void cvt_split(
    const float4* __restrict__ x, __nv_bfloat162* __restrict__ h,
    __nv_bfloat162* __restrict__ l, int n4)
{
    int i = blockIdx.x * 256 + threadIdx.x;
    if (i >= n4) return;
    float4 v = x[i];
    __nv_bfloat16 h0 = __float2bfloat16(v.x), h1 = __float2bfloat16(v.y);
    __nv_bfloat16 h2 = __float2bfloat16(v.z), h3 = __float2bfloat16(v.w);
    __nv_bfloat16 l0 = __float2bfloat16(v.x - __bfloat162float(h0));
    __nv_bfloat16 l1 = __float2bfloat16(v.y - __bfloat162float(h1));
    __nv_bfloat16 l2 = __float2bfloat16(v.z - __bfloat162float(h2));
    __nv_bfloat16 l3 = __float2bfloat16(v.w - __bfloat162float(h3));
    h[2 * i]     = __halves2bfloat162(h0, h1);
    h[2 * i + 1] = __halves2bfloat162(h2, h3);
    l[2 * i]     = __halves2bfloat162(l0, l1);
    l[2 * i + 1] = __halves2bfloat162(l2, l3);
}

// ---------------------------------------------------------------------------
// Transpose + split: w[K,N] fp32 -> hT[N,K], lT[N,K] bf16
// ---------------------------------------------------------------------------
__global__ void cvt_trans(const float* __restrict__ w,
                          __nv_bfloat16* __restrict__ h,
                          __nv_bfloat16* __restrict__ l, int K, int N)
{
    __shared__ float t[32][33];
    int n0 = blockIdx.x * 32, k0 = blockIdx.y * 32;
    int tx = threadIdx.x, ty = threadIdx.y;
#pragma unroll
    for (int i = 0; i < 4; i++)
        t[ty + 8 * i][tx] = w[(size_t)(k0 + ty + 8 * i) * N + n0 + tx];
    __syncthreads();
#pragma unroll
    for (int i = 0; i < 4; i++) {
        float v = t[tx][ty + 8 * i];
        __nv_bfloat16 hb = __float2bfloat16(v);
        __nv_bfloat16 lb = __float2bfloat16(v - __bfloat162float(hb));
        size_t o = (size_t)(n0 + ty + 8 * i) * K + k0 + tx;
        h[o] = hb;
        l[o] = lb;
    }
}

// ---------------------------------------------------------------------------
// bf16x3 HMMA GEMM:  C = (Ah+Al)[M,K] @ (Bh+Bl)[N,K]^T + bias[N]
// CTA 128x128, 8 warps (2M x 4N), warp tile 64x32, KC=64, cp.async x2 buffer.
// out_bf16 == 0: write fp32 C;  == 1: write bf16 hi/lo (Ch, Cl).
// ---------------------------------------------------------------------------
#define KC       64
#define RSTRIDE  144
#define ARRB     (128 * RSTRIDE)
#define STAGEB   (4 * ARRB)
#define GSMEM    (2 * STAGEB)

__device__ __forceinline__ void g_load_stage(
    uint32_t sb, int st, const __nv_bfloat16* Ah, const __nv_bfloat16* Al,
    const __nv_bfloat16* Bh, const __nv_bfloat16* Bl,
    int m0, int n0, int k0, int K, int tid)
{
    uint32_t base = sb + (uint32_t)st * STAGEB;
#pragma unroll 4
    for (int i = tid; i < 4096; i += 256) {
        int arr = i >> 10;
        int idx = i & 1023;
        int row = idx >> 3;
        int c   = idx & 7;
        const __nv_bfloat16* g;
        if (arr == 0)      g = Ah + (size_t)(m0 + row) * K;
        else if (arr == 1) g = Al + (size_t)(m0 + row) * K;
        else if (arr == 2) g = Bh + (size_t)(n0 + row) * K;
        else               g = Bl + (size_t)(n0 + row) * K;
        const __nv_bfloat16* gp = g + k0 + c * 8;
        uint32_t sm = base + (uint32_t)arr * ARRB + (uint32_t)row * RSTRIDE + c * 16;
        CP_ASYNC16(sm, gp);
    }
}

__global__ __launch_bounds__(256, 1)
void gemm_bf16x3(const __nv_bfloat16* __restrict__ Ah,
                 const __nv_bfloat16* __restrict__ Al,
                 const __nv_bfloat16* __restrict__ Bh,
                 const __nv_bfloat16* __restrict__ Bl,
                 const float* __restrict__ bias, float* __restrict__ C,
                 __nv_bfloat16* __restrict__ Ch, __nv_bfloat16* __restrict__ Cl,
                 int M, int N, int K, int out_bf16)
{
    extern __shared__ char smem[];
    uint32_t sb = smem_u32(smem);
    const int tid = threadIdx.x;
    const int wid = tid >> 5;
    const int lane = tid & 31;
    const int wm = wid & 1;
    const int wn = wid >> 1;
    const int m0 = blockIdx.y * 128;
    const int n0 = blockIdx.x * 128;

    float acc[4][4][4];
#pragma unroll
    for (int mi = 0; mi < 4; mi++)
#pragma unroll
        for (int ni = 0; ni < 4; ni++)
#pragma unroll
            for (int j = 0; j < 4; j++) acc[mi][ni][j] = 0.0f;

    const int S = K / KC;

    g_load_stage(sb, 0, Ah, Al, Bh, Bl, m0, n0, 0, K, tid);
    CP_COMMIT();

    const int g8 = lane >> 3, r8 = lane & 7;
    const uint32_t aoff = (uint32_t)((wm * 64 + (g8 & 1) * 8 + r8) * RSTRIDE
                                     + (g8 >> 1) * 16);
    const uint32_t boff = (uint32_t)((wn * 32 + (g8 >> 1) * 8 + r8) * RSTRIDE
                                     + (g8 & 1) * 16);

    for (int s = 0; s < S; s++) {
        if (s + 1 < S) {
            g_load_stage(sb, (s + 1) & 1, Ah, Al, Bh, Bl, m0, n0,
                         (s + 1) * KC, K, tid);
            CP_COMMIT();
            CP_WAIT(1);
        } else {
            CP_WAIT(0);
        }
        __syncthreads();

        uint32_t sA  = sb + (uint32_t)(s & 1) * STAGEB;
        uint32_t sAl = sA + ARRB;
        uint32_t sB  = sA + 2 * ARRB;
        uint32_t sBl = sA + 3 * ARRB;

#pragma unroll
        for (int ks = 0; ks < 4; ks++) {
            const uint32_t kb = ks * 32;
            uint32_t ah[4][4], al[4][4];
#pragma unroll
            for (int mi = 0; mi < 4; mi++) {
                uint32_t o = aoff + (uint32_t)(mi * 16 * RSTRIDE) + kb;
                ldm_x4(ah[mi], sA + o);
                ldm_x4(al[mi], sAl + o);
            }
            uint32_t bh[2][4], bl[2][4];
#pragma unroll
            for (int nb = 0; nb < 2; nb++) {
                uint32_t o = boff + (uint32_t)(nb * 16 * RSTRIDE) + kb;
                ldm_x4(bh[nb], sB + o);
                ldm_x4(bl[nb], sBl + o);
            }
#pragma unroll
            for (int mi = 0; mi < 4; mi++) {
#pragma unroll
                for (int ni = 0; ni < 4; ni++) {
                    float* d = acc[mi][ni];
                    const uint32_t* Bh2 = &bh[ni >> 1][(ni & 1) * 2];
                    const uint32_t* Bl2 = &bl[ni >> 1][(ni & 1) * 2];
                    mma16816(d, ah[mi], Bh2);
                    mma16816(d, ah[mi], Bl2);
                    mma16816(d, al[mi], Bh2);
                }
            }
        }
        __syncthreads();
    }

    const int er = lane >> 2;
    const int ec = (lane & 3) * 2;
#pragma unroll
    for (int mi = 0; mi < 4; mi++) {
        int row = m0 + wm * 64 + mi * 16 + er;
#pragma unroll
        for (int ni = 0; ni < 4; ni++) {
            int col = n0 + wn * 32 + ni * 8 + ec;
            float bx = bias[col], by = bias[col + 1];
            float v0 = acc[mi][ni][0] + bx, v1 = acc[mi][ni][1] + by;
            float v2 = acc[mi][ni][2] + bx, v3 = acc[mi][ni][3] + by;
            if (out_bf16) {
                __nv_bfloat16 h0 = __float2bfloat16(v0), h1 = __float2bfloat16(v1);
                __nv_bfloat16 h2 = __float2bfloat16(v2), h3 = __float2bfloat16(v3);
                uint32_t hv0, hv1, lv0, lv1;
                { __nv_bfloat162 t2 = __halves2bfloat162(h0, h1); hv0 = *(uint32_t*)&t2; }
                { __nv_bfloat162 t2 = __halves2bfloat162(h2, h3); hv1 = *(uint32_t*)&t2; }
                lv0 = pack_bf2(v0 - __bfloat162float(h0), v1 - __bfloat162float(h1));
                lv1 = pack_bf2(v2 - __bfloat162float(h2), v3 - __bfloat162float(h3));
                *(uint32_t*)(Ch + (size_t)row * N + col)       = hv0;
                *(uint32_t*)(Ch + (size_t)(row + 8) * N + col) = hv1;
                *(uint32_t*)(Cl + (size_t)row * N + col)       = lv0;
                *(uint32_t*)(Cl + (size_t)(row + 8) * N + col) = lv1;
            } else {
                *(float2*)(C + (size_t)row * N + col)       = make_float2(v0, v1);
                *(float2*)(C + (size_t)(row + 8) * N + col) = make_float2(v2, v3);
            }
        }
    }
}

// ---------------------------------------------------------------------------
// HMMA attention, bf16x3 both matmuls, sum-normalized softmax (no max pass:
// scores/16 are O(1), exp cannot overflow fp32).
// CTA = (b, h, 64 q-rows); 8 warps; Li processed in 9 chunks of 64 keys.
// ---------------------------------------------------------------------------
#define AQS  528                           // Q/K/V smem row stride (bytes)
#define APS  144                           // P smem row stride (bytes)
#define AT_Q   0
#define AT_QL  (64 * AQS)                  // 33792
#define AT_K   (2 * 64 * AQS)
#define AT_KL  (3 * 64 * AQS)
#define AT_V   (4 * 64 * AQS)
#define AT_VL  (5 * 64 * AQS)
#define AT_PH  (6 * 64 * AQS)              // 202752
#define AT_PL  (AT_PH + 64 * APS)
#define AT_RS  (AT_PH + 2 * 64 * APS)      // 221184
#define AT_SMEM (AT_RS + 64 * 4)           // 221440

__global__ __launch_bounds__(256, 1) void attn_hmma(
    const __nv_bfloat16* __restrict__ qh, const __nv_bfloat16* __restrict__ ql,
    const __nv_bfloat16* __restrict__ kh, const __nv_bfloat16* __restrict__ kl,
    const __nv_bfloat16* __restrict__ vh, const __nv_bfloat16* __restrict__ vl,
    __nv_bfloat16* __restrict__ xh, __nv_bfloat16* __restrict__ xl)
{
    extern __shared__ char smem[];
    uint32_t sb = smem_u32(smem);
    float* rowsum = (float*)(smem + AT_RS);

    const int tid = threadIdx.x, lane = tid & 31, wid = tid >> 5;
    const int b = blockIdx.z, h = blockIdx.y;
    const int q0 = blockIdx.x * 64;
    const size_t hc = (size_t)h * HDIM;

    // Q hi/lo: 64 rows x 256 cols
    for (int i = tid; i < 4096; i += 256) {
        int arr = i >> 11, idx = i & 2047, row = idx >> 5, c = idx & 31;
        const __nv_bfloat16* g = (arr ? ql : qh)
            + ((size_t)(b * LT + q0 + row)) * HID + hc + c * 8;
        CP_ASYNC16(sb + (arr ? AT_QL : AT_Q) + row * AQS + c * 16, g);
    }
    CP_COMMIT();
    if (tid < 64) rowsum[tid] = 0.0f;

    const int g8 = lane >> 3, r8 = lane & 7;
    const int wq = wid >> 1;         // q-group (0..3): rows [wq*16, +16)
    const int wk = wid & 1;          // QK: key half;  PV: d half
    const int er = lane >> 2, ec2 = (lane & 3) * 2;

    const uint32_t aoA = (uint32_t)((wq * 16 + (g8 & 1) * 8 + r8) * AQS + (g8 >> 1) * 16);
    const uint32_t boB = (uint32_t)((wk * 32 + (g8 >> 1) * 8 + r8) * AQS + (g8 & 1) * 16);
    const uint32_t aoP = (uint32_t)((wq * 16 + (g8 & 1) * 8 + r8) * APS + (g8 >> 1) * 16);

    float acc2[16][4];
#pragma unroll
    for (int ni = 0; ni < 16; ni++)
#pragma unroll
        for (int j = 0; j < 4; j++) acc2[ni][j] = 0.0f;

    for (int ch = 0; ch < 9; ch++) {
        __syncthreads();   // previous PV done: safe to overwrite K/V
        for (int i = tid; i < 8192; i += 256) {
            int arr = i >> 11, idx = i & 2047, row = idx >> 5, c = idx & 31;
            const __nv_bfloat16* gb;
            uint32_t so;
            if (arr == 0)      { gb = kh; so = AT_K;  }
            else if (arr == 1) { gb = kl; so = AT_KL; }
            else if (arr == 2) { gb = vh; so = AT_V;  }
            else               { gb = vl; so = AT_VL; }
            const __nv_bfloat16* g = gb
                + ((size_t)(b * LI + ch * 64 + row)) * HID + hc + c * 8;
            CP_ASYNC16(sb + so + row * AQS + c * 16, g);
        }
        CP_COMMIT();
        CP_WAIT(0);
        __syncthreads();   // K/V (and Q on first iter) visible

        // ---- scores S[16q x 32keys] per warp ----
        float s[4][4];
#pragma unroll
        for (int ni = 0; ni < 4; ni++)
#pragma unroll
            for (int j = 0; j < 4; j++) s[ni][j] = 0.0f;

#pragma unroll 4
        for (int kk = 0; kk < 16; kk++) {
            uint32_t ka = kk * 32;
            uint32_t ahf[4], alf[4];
            ldm_x4(ahf, sb + AT_Q + aoA + ka);
            ldm_x4(alf, sb + AT_QL + aoA + ka);
            uint32_t bhf[2][4], blf[2][4];
#pragma unroll
            for (int nb = 0; nb < 2; nb++) {
                uint32_t o = boB + nb * 16 * AQS + ka;
                ldm_x4(bhf[nb], sb + AT_K + o);
                ldm_x4(blf[nb], sb + AT_KL + o);
            }
#pragma unroll
            for (int ni = 0; ni < 4; ni++) {
                const uint32_t* B2h = &bhf[ni >> 1][(ni & 1) * 2];
                const uint32_t* B2l = &blf[ni >> 1][(ni & 1) * 2];
                mma16816(s[ni], ahf, B2h);
                mma16816(s[ni], ahf, B2l);
                mma16816(s[ni], alf, B2h);
            }
        }

        // ---- exp, row sums, P -> smem (hi/lo) ----
        float rs0 = 0.0f, rs1 = 0.0f;
#pragma unroll
        for (int ni = 0; ni < 4; ni++) {
            float p0 = __expf(s[ni][0] * 0.0625f);
            float p1 = __expf(s[ni][1] * 0.0625f);
            float p2 = __expf(s[ni][2] * 0.0625f);
            float p3 = __expf(s[ni][3] * 0.0625f);
            rs0 += p0 + p1;
            rs1 += p2 + p3;
            __nv_bfloat16 h0 = __float2bfloat16(p0), h1 = __float2bfloat16(p1);
            __nv_bfloat16 h2 = __float2bfloat16(p2), h3 = __float2bfloat16(p3);
            uint32_t hv0, hv1;
            { __nv_bfloat162 t2 = __halves2bfloat162(h0, h1); hv0 = *(uint32_t*)&t2; }
            { __nv_bfloat162 t2 = __halves2bfloat162(h2, h3); hv1 = *(uint32_t*)&t2; }
            uint32_t lv0 = pack_bf2(p0 - __bfloat162float(h0), p1 - __bfloat162float(h1));
            uint32_t lv1 = pack_bf2(p2 - __bfloat162float(h2), p3 - __bfloat162float(h3));
            int key = wk * 32 + ni * 8 + ec2;
            uint32_t po0 = (uint32_t)((wq * 16 + er) * APS + key * 2);
            uint32_t po1 = (uint32_t)((wq * 16 + er + 8) * APS + key * 2);
            *(uint32_t*)(smem + AT_PH + po0) = hv0;
            *(uint32_t*)(smem + AT_PH + po1) = hv1;
            *(uint32_t*)(smem + AT_PL + po0) = lv0;
            *(uint32_t*)(smem + AT_PL + po1) = lv1;
        }
        rs0 += __shfl_xor_sync(0xffffffffu, rs0, 1);
        rs0 += __shfl_xor_sync(0xffffffffu, rs0, 2);
        rs1 += __shfl_xor_sync(0xffffffffu, rs1, 1);
        rs1 += __shfl_xor_sync(0xffffffffu, rs1, 2);
        if ((lane & 3) == 0) {
            atomicAdd(&rowsum[wq * 16 + er], rs0);
            atomicAdd(&rowsum[wq * 16 + er + 8], rs1);
        }
        __syncthreads();   // P visible

        // ---- PV: X[16q x 128d] per warp over 64 keys ----
#pragma unroll
        for (int kk = 0; kk < 4; kk++) {
            uint32_t pa = kk * 32;
            uint32_t phf[4], plf[4];
            ldm_x4(phf, sb + AT_PH + aoP + pa);
            ldm_x4(plf, sb + AT_PL + aoP + pa);
#pragma unroll
            for (int nb = 0; nb < 8; nb++) {
                int krow = kk * 16 + (g8 & 1) * 8 + r8;
                int dcol = wk * 128 + nb * 16 + (g8 >> 1) * 8;
                uint32_t vo = (uint32_t)(krow * AQS + dcol * 2);
                uint32_t bvh[4], bvl[4];
                ldm_x4t(bvh, sb + AT_V + vo);
                ldm_x4t(bvl, sb + AT_VL + vo);
                mma16816(acc2[2 * nb],     phf, &bvh[0]);
                mma16816(acc2[2 * nb],     phf, &bvl[0]);
                mma16816(acc2[2 * nb],     plf, &bvh[0]);
                mma16816(acc2[2 * nb + 1], phf, &bvh[2]);
                mma16816(acc2[2 * nb + 1], phf, &bvl[2]);
                mma16816(acc2[2 * nb + 1], plf, &bvh[2]);
            }
        }
    }
    __syncthreads();

    // ---- normalize + write xh/xl ----
    float inv0 = 1.0f / rowsum[wq * 16 + er];
    float inv1 = 1.0f / rowsum[wq * 16 + er + 8];
    size_t grow0 = ((size_t)(b * LT + q0 + wq * 16 + er)) * HID + hc;
    size_t grow1 = grow0 + (size_t)8 * HID;
#pragma unroll
    for (int ni = 0; ni < 16; ni++) {
        int col = wk * 128 + ni * 8 + ec2;
        float v0 = acc2[ni][0] * inv0, v1 = acc2[ni][1] * inv0;
        float v2 = acc2[ni][2] * inv1, v3 = acc2[ni][3] * inv1;
        __nv_bfloat16 h0 = __float2bfloat16(v0), h1 = __float2bfloat16(v1);
        __nv_bfloat16 h2 = __float2bfloat16(v2), h3 = __float2bfloat16(v3);
        uint32_t hv0, hv1;
        { __nv_bfloat162 t2 = __halves2bfloat162(h0, h1); hv0 = *(uint32_t*)&t2; }
        { __nv_bfloat162 t2 = __halves2bfloat162(h2, h3); hv1 = *(uint32_t*)&t2; }
        uint32_t lv0 = pack_bf2(v0 - __bfloat162float(h0), v1 - __bfloat162float(h1));
        uint32_t lv1 = pack_bf2(v2 - __bfloat162float(h2), v3 - __bfloat162float(h3));
        *(uint32_t*)(xh + grow0 + col) = hv0;
        *(uint32_t*)(xh + grow1 + col) = hv1;
        *(uint32_t*)(xl + grow0 + col) = lv0;
        *(uint32_t*)(xl + grow1 + col) = lv1;
    }
}

// ---------------------------------------------------------------------------
// Fused FF + residual + LayerNorm
// ---------------------------------------------------------------------------
__global__ __launch_bounds__(256) void ffln_kernel(
    const float* __restrict__ O, const float* __restrict__ w1,
    const float* __restrict__ b1, const float* __restrict__ w2,
    const float* __restrict__ b2, const float* __restrict__ gamma,
    const float* __restrict__ beta, float* __restrict__ out)
{
    __shared__ float xs[4][TEXTD];
    __shared__ float hs[4][FFD];
    __shared__ float reds[4][8], redq[4][8];
    __shared__ float s_mu[4], s_rstd[4];

    const int tid = threadIdx.x;
    const size_t row0 = (size_t)blockIdx.x * 4;

    for (int i = tid; i < 4 * (TEXTD / 4); i += 256) {
        int r = i / (TEXTD / 4), c = (i % (TEXTD / 4)) * 4;
        *(float4*)&xs[r][c] = *(const float4*)(O + (row0 + r) * TEXTD + c);
    }
    __syncthreads();

    if (tid < FFD) {
        const int u = tid;
        float a0 = b1[u], a1 = b1[u], a2 = b1[u], a3 = b1[u];
        for (int dd = 0; dd < TEXTD; dd++) {
            float w = w1[dd * FFD + u];
            a0 += xs[0][dd] * w;
            a1 += xs[1][dd] * w;
            a2 += xs[2][dd] * w;
            a3 += xs[3][dd] * w;
        }
        hs[0][u] = fmaxf(a0, 0.0f);
        hs[1][u] = fmaxf(a1, 0.0f);
        hs[2][u] = fmaxf(a2, 0.0f);
        hs[3][u] = fmaxf(a3, 0.0f);
    }
    __syncthreads();

    float acc[4][3];
#pragma unroll
    for (int r = 0; r < 4; r++)
#pragma unroll
        for (int c = 0; c < 3; c++) acc[r][c] = 0.0f;

    for (int u = 0; u < FFD; u++) {
        float wa = w2[(size_t)u * TEXTD + tid];
        float wb = w2[(size_t)u * TEXTD + tid + 256];
        float wc = w2[(size_t)u * TEXTD + tid + 512];
#pragma unroll
        for (int r = 0; r < 4; r++) {
            float hv = hs[r][u];
            acc[r][0] += hv * wa;
            acc[r][1] += hv * wb;
            acc[r][2] += hv * wc;
        }
    }

    float yv[4][3];
#pragma unroll
    for (int r = 0; r < 4; r++) {
#pragma unroll
        for (int c = 0; c < 3; c++) {
            int n = tid + c * 256;
            yv[r][c] = xs[r][n] + acc[r][c] + b2[n];
        }
    }

    const int lane = tid & 31, wd = tid >> 5;
#pragma unroll
    for (int r = 0; r < 4; r++) {
        float s = yv[r][0] + yv[r][1] + yv[r][2];
        float q = yv[r][0] * yv[r][0] + yv[r][1] * yv[r][1] + yv[r][2] * yv[r][2];
#pragma unroll
        for (int o = 16; o; o >>= 1) {
            s += __shfl_xor_sync(0xffffffffu, s, o);
            q += __shfl_xor_sync(0xffffffffu, q, o);
        }
        if (lane == 0) { reds[r][wd] = s; redq[r][wd] = q; }
    }
    __syncthreads();
    if (tid < 4) {
        float s = 0.0f, q = 0.0f;
#pragma unroll
        for (int w = 0; w < 8; w++) { s += reds[tid][w]; q += redq[tid][w]; }
        float m = s * (1.0f / TEXTD);
        float v = q * (1.0f / TEXTD) - m * m;
        s_mu[tid] = m;
        s_rstd[tid] = rsqrtf(v + 1e-5f);
    }
    __syncthreads();

#pragma unroll
    for (int r = 0; r < 4; r++) {
        float m = s_mu[r], rs = s_rstd[r];
#pragma unroll
        for (int c = 0; c < 3; c++) {
            int n = tid + c * 256;
            out[(row0 + r) * TEXTD + n] = (yv[r][c] - m) * rs * gamma[n] + beta[n];
        }
    }
}

// ---------------------------------------------------------------------------
// Launcher
// ---------------------------------------------------------------------------
extern "C" void kernel_launch(void* const* d_in, const int* in_sizes, int n_in,
                              void* d_out, int out_size)
{
    const float* text  = (const float*)d_in[0];
    const float* image = (const float*)d_in[1];
    const float* wq = (const float*)d_in[2];
    const float* bq = (const float*)d_in[3];
    const float* wk = (const float*)d_in[4];
    const float* bk = (const float*)d_in[5];
    const float* wv = (const float*)d_in[6];
    const float* bv = (const float*)d_in[7];
    const float* wr = (const float*)d_in[8];
    const float* br = (const float*)d_in[9];
    const float* w1 = (const float*)d_in[10];
    const float* b1 = (const float*)d_in[11];
    const float* w2 = (const float*)d_in[12];
    const float* b2 = (const float*)d_in[13];
    const float* gamma = (const float*)d_in[14];
    const float* beta  = (const float*)d_in[15];
    float* out = (float*)d_out;

    float* Op;
    cudaGetSymbolAddress((void**)&Op, g_O);

    __nv_bfloat16 *th, *tl, *ih, *il;
    __nv_bfloat16 *qh, *ql, *kh, *kl, *vh, *vl, *xh, *xl;
    __nv_bfloat16 *wqh, *wql, *wkh, *wkl, *wvh, *wvl, *wrh, *wrl;
    cudaGetSymbolAddress((void**)&th, g_th);
    cudaGetSymbolAddress((void**)&tl, g_tl);
    cudaGetSymbolAddress((void**)&ih, g_ih);
    cudaGetSymbolAddress((void**)&il, g_il);
    cudaGetSymbolAddress((void**)&qh, g_qh);
    cudaGetSymbolAddress((void**)&ql, g_ql);
    cudaGetSymbolAddress((void**)&kh, g_kh);
    cudaGetSymbolAddress((void**)&kl, g_kl);
    cudaGetSymbolAddress((void**)&vh, g_vh);
    cudaGetSymbolAddress((void**)&vl, g_vl);
    cudaGetSymbolAddress((void**)&xh, g_xh);
    cudaGetSymbolAddress((void**)&xl, g_xl);
    cudaGetSymbolAddress((void**)&wqh, g_wqh);
    cudaGetSymbolAddress((void**)&wql, g_wql);
    cudaGetSymbolAddress((void**)&wkh, g_wkh);
    cudaGetSymbolAddress((void**)&wkl, g_wkl);
    cudaGetSymbolAddress((void**)&wvh, g_wvh);
    cudaGetSymbolAddress((void**)&wvl, g_wvl);
    cudaGetSymbolAddress((void**)&wrh, g_wrh);
    cudaGetSymbolAddress((void**)&wrl, g_wrl);

    cudaFuncSetAttribute(gemm_bf16x3, cudaFuncAttributeMaxDynamicSharedMemorySize,
                         GSMEM);
    cudaFuncSetAttribute(attn_hmma, cudaFuncAttributeMaxDynamicSharedMemorySize,
                         AT_SMEM);

    // --- conversions ---
    {
        int n4 = MQ * TEXTD / 4;
        cvt_split<<<(n4 + 255) / 256, 256>>>((const float4*)text,
            (__nv_bfloat162*)th, (__nv_bfloat162*)tl, n4);
    }
    {
        int n4 = MK * IMGD / 4;
        cvt_split<<<(n4 + 255) / 256, 256>>>((const float4*)image,
            (__nv_bfloat162*)ih, (__nv_bfloat162*)il, n4);
    }
    cvt_trans<<<dim3(HID / 32, TEXTD / 32), dim3(32, 8)>>>(wq, wqh, wql, TEXTD, HID);
    cvt_trans<<<dim3(HID / 32, IMGD / 32),  dim3(32, 8)>>>(wk, wkh, wkl, IMGD, HID);
    cvt_trans<<<dim3(HID / 32, IMGD / 32),  dim3(32, 8)>>>(wv, wvh, wvl, IMGD, HID);
    cvt_trans<<<dim3(TEXTD / 32, HID / 32), dim3(32, 8)>>>(wr, wrh, wrl, HID, TEXTD);

    // --- projection GEMMs -> bf16 hi/lo ---
    gemm_bf16x3<<<dim3(HID / 128, MQ / 128), 256, GSMEM>>>(
        th, tl, wqh, wql, bq, nullptr, qh, ql, MQ, HID, TEXTD, 1);
    gemm_bf16x3<<<dim3(HID / 128, MK / 128), 256, GSMEM>>>(
        ih, il, wkh, wkl, bk, nullptr, kh, kl, MK, HID, IMGD, 1);
    gemm_bf16x3<<<dim3(HID / 128, MK / 128), 256, GSMEM>>>(
        ih, il, wvh, wvl, bv, nullptr, vh, vl, MK, HID, IMGD, 1);

    // --- HMMA attention -> xh/xl ---
    attn_hmma<<<dim3(LT / 64, HEADS, BATCH), 256, AT_SMEM>>>(
        qh, ql, kh, kl, vh, vl, xh, xl);

    // --- out projection -> fp32 ---
    gemm_bf16x3<<<dim3(TEXTD / 128, MQ / 128), 256, GSMEM>>>(
        xh, xl, wrh, wrl, br, Op, nullptr, nullptr, MQ, TEXTD, HID, 0);

    // --- FF + residual + LayerNorm ---
    ffln_kernel<<<MQ / 4, 256>>>(Op, w1, b1, w2, b2, gamma, beta, out);
}